// round 14
// baseline (speedup 1.0000x reference)
#include <cuda_runtime.h>
#include <cuda_fp16.h>
#include <cstdint>

// ===========================================================================
// ScaledAttention on GB300 (compute_103 target -> legacy mma.sync path).
// R14 = R13 (best, 354.9us) + OUT phase split into 128x64 tiles using a
// 64x32-warp GEMM body (R10's proven inner loop) -> 4416 bids, 14.92 waves,
// nearly-full last wave and half-length drain tiles.
// One dependency-overlapped mega-kernel (bid-ordered, counter-synced).
// fp16 operands, fp32 accumulate, main GEMMs warp 64x64 CTA 128x128,
// 2 CTAs/SM. B=4, Lq=Lm=2048, D=1024.
// ===========================================================================

#define STAGES 3
#define BM 128
#define BN 128
#define BK 64
#define NTHREADS 128
#define A_STAGE (BM * BK * 2)                       // 16384 B
#define B_STAGE (BN * BK * 2)                       // 16384 B
#define B_STAGE64 (64 * BK * 2)                     // 8192 B (out-phase tiles)
#define SMEM_BYTES (STAGES * (A_STAGE + B_STAGE))   // 98304 B -> 2 CTAs/SM

// Scratch (allocation-free rule: __device__ globals)
__device__ __half g_Q [8192 * 1024];
__device__ __half g_K [8192 * 1024];
__device__ __half g_VT[4][1024 * 2048];    // V^T per batch: [d][m]
__device__ __half g_O [8192 * 1024];
__device__ __half g_S [4LL * 2048 * 2048]; // E = exp(logit-4)
__device__ float  g_Ssum[4 * 2048];
__device__ __half g_Xh[8192 * 1024];
__device__ __half g_Mh[8192 * 1024];
__device__ __half g_Wh[4][1024 * 1024];
// Counters:
// [0..3]    W conv (tgt16)
// [6]       Ssum zero (tgt64)
// [8..71]   X conv per-mb (128-row slice; tgt2)
// [72..135] M conv per-mb (tgt2)
// [136..199] Q rowblk (tgt8)
// [200..263] K rowblk (tgt8)
// [264..295] VT (b*8+dblk) (tgt16)
// [296..359] E rowblk (tgt16)
// [360..423] O rowblk (tgt8)
__device__ int g_ctr[424];

__device__ __forceinline__ uint32_t smem_u32(const void* p) {
    uint32_t a;
    asm("{ .reg .u64 t; cvta.to.shared.u64 t, %1; cvt.u32.u64 %0, t; }"
        : "=r"(a) : "l"(p));
    return a;
}
__device__ __forceinline__ void cp16(uint32_t dst, const void* src) {
    asm volatile("cp.async.cg.shared.global [%0], [%1], 16;"
                 :: "r"(dst), "l"(src) : "memory");
}
__device__ __forceinline__ void cp_commit() {
    asm volatile("cp.async.commit_group;" ::: "memory");
}
template <int N>
__device__ __forceinline__ void cp_wait() {
    asm volatile("cp.async.wait_group %0;" :: "n"(N) : "memory");
}
__device__ __forceinline__ void ldsm4(uint32_t* r, uint32_t addr) {
    asm volatile("ldmatrix.sync.aligned.m8n8.x4.shared.b16 {%0,%1,%2,%3}, [%4];"
                 : "=r"(r[0]), "=r"(r[1]), "=r"(r[2]), "=r"(r[3]) : "r"(addr));
}
__device__ __forceinline__ void mma_f16(float* c, const uint32_t* a, const uint32_t* b) {
    asm volatile(
        "mma.sync.aligned.m16n8k16.row.col.f32.f16.f16.f32 "
        "{%0,%1,%2,%3}, {%4,%5,%6,%7}, {%8,%9}, {%0,%1,%2,%3};"
        : "+f"(c[0]), "+f"(c[1]), "+f"(c[2]), "+f"(c[3])
        : "r"(a[0]), "r"(a[1]), "r"(a[2]), "r"(a[3]), "r"(b[0]), "r"(b[1]));
}

// Consumer: acquire-spin until *c >= tgt.
__device__ __forceinline__ void waitc(const int* c, int tgt) {
    if (threadIdx.x == 0) {
        int v;
        for (;;) {
            asm volatile("ld.global.acquire.gpu.b32 %0, [%1];" : "=r"(v) : "l"(c));
            if (v >= tgt) break;
            __nanosleep(128);
        }
    }
    __syncthreads();
}
// Producer: fence stores, then one thread bumps the counter.
__device__ __forceinline__ void bump(int* c) {
    __threadfence();
    __syncthreads();
    if (threadIdx.x == 0) atomicAdd(c, 1);
}

// ---------------------------------------------------------------------------
// Main GEMM body (R11/R13 proven): C tile [128,128] = A[M,K] @ B^T.
// 4 warps in 2x2 of 64x64.
// OUTMODE 0: fp16 C row-major
// OUTMODE 3: fp16 VT store (r0 = global row b*2048+m -> VT[b][c][m])
// OUTMODE 4: logits: store exp(acc-4) fp16 + atomicAdd row sums into aux
// OUTMODE 5: PV: multiply by 1/aux[row] before fp16 store
// ---------------------------------------------------------------------------
template <int OUTMODE>
__device__ __forceinline__ void gemm_body(
    const __half* __restrict__ Ab, const __half* __restrict__ Bb,
    void* __restrict__ Cv, int K, int ldA, int ldB, int ldC,
    int bm0, int bn0, float* __restrict__ aux)
{
    extern __shared__ char sm[];
    char* smA = sm;
    char* smB = sm + STAGES * A_STAGE;

    const int tid = threadIdx.x, wid = tid >> 5, lane = tid & 31;
    const int g = lane >> 2, tg = lane & 3;
    const int m0 = (wid >> 1) * 64;   // 2x2 warp grid
    const int n0 = (wid & 1) * 64;

    const uint32_t smAu = smem_u32(smA);
    const uint32_t smBu = smem_u32(smB);

    auto issue = [&](int kt, int buf) {
#pragma unroll
        for (int p = 0; p < 8; p++) {
            const int id = p * NTHREADS + tid;
            const int row = id >> 3, ch = id & 7;
            cp16(smAu + buf * A_STAGE + row * 128 + ((ch ^ (row & 7)) * 16),
                 Ab + (long long)(bm0 + row) * ldA + kt * BK + ch * 8);
        }
#pragma unroll
        for (int p = 0; p < 8; p++) {
            const int id = p * NTHREADS + tid;
            const int row = id >> 3, ch = id & 7;
            cp16(smBu + buf * B_STAGE + row * 128 + ((ch ^ (row & 7)) * 16),
                 Bb + (long long)(bn0 + row) * ldB + kt * BK + ch * 8);
        }
        cp_commit();
    };

    const int akc = lane >> 4;
    const int bkc = (lane >> 3) & 1;
    uint32_t aOff[4]; int aR7[4];
#pragma unroll
    for (int mt = 0; mt < 4; mt++) {
        const int r = m0 + mt * 16 + (lane & 15);
        aOff[mt] = r * 128; aR7[mt] = r & 7;
    }
    uint32_t bOff[4]; int bR7[4];
#pragma unroll
    for (int j = 0; j < 4; j++) {
        const int r = n0 + j * 16 + (lane & 7) + ((lane >> 4) << 3);
        bOff[j] = r * 128; bR7[j] = r & 7;
    }

    float acc[4][8][4];
#pragma unroll
    for (int mt = 0; mt < 4; mt++)
#pragma unroll
        for (int nt = 0; nt < 8; nt++)
#pragma unroll
            for (int i = 0; i < 4; i++) acc[mt][nt][i] = 0.f;

    const int NKT = K / BK;
    issue(0, 0);
    issue(1, 1);

    for (int kt = 0; kt < NKT; kt++) {
        cp_wait<STAGES - 2>();
        __syncthreads();   // single barrier per stage (skew-proof)

        const int buf = kt % STAGES;
        const uint32_t ab = smAu + buf * A_STAGE;
        const uint32_t bb = smBu + buf * B_STAGE;

        uint32_t af[2][4][4], bf[2][4][4];
        auto ldfr = [&](int ks, int slot) {
#pragma unroll
            for (int mt = 0; mt < 4; mt++)
                ldsm4(af[slot][mt], ab + aOff[mt] + (((ks * 2 + akc) ^ aR7[mt]) * 16));
#pragma unroll
            for (int j = 0; j < 4; j++)
                ldsm4(bf[slot][j], bb + bOff[j] + (((ks * 2 + bkc) ^ bR7[j]) * 16));
        };

        ldfr(0, 0);
        const int nxt = kt + STAGES - 1;
        if (nxt < NKT) issue(nxt, nxt % STAGES);
        else cp_commit();

#pragma unroll
        for (int ks = 0; ks < 4; ks++) {
            const int cur = ks & 1;
            if (ks < 3) ldfr(ks + 1, cur ^ 1);
#pragma unroll
            for (int mt = 0; mt < 4; mt++)
#pragma unroll
                for (int nt = 0; nt < 8; nt++)
                    mma_f16(acc[mt][nt], af[cur][mt], &bf[cur][nt >> 1][(nt & 1) * 2]);
        }
    }

    // Epilogue
#pragma unroll
    for (int mt = 0; mt < 4; mt++) {
        const int r0 = bm0 + m0 + mt * 16 + g;
        float inv0 = 1.f, inv1 = 1.f;
        if (OUTMODE == 5) {
            inv0 = 1.0f / aux[r0];
            inv1 = 1.0f / aux[r0 + 8];
        }
        float rsum0 = 0.f, rsum1 = 0.f;
#pragma unroll
        for (int nt = 0; nt < 8; nt++) {
            const int c = bn0 + n0 + nt * 8 + 2 * tg;
            float v0 = acc[mt][nt][0], v1 = acc[mt][nt][1];
            float v2 = acc[mt][nt][2], v3 = acc[mt][nt][3];
            if (OUTMODE == 0) {
                __half* C = (__half*)Cv;
                __half2 h0 = __floats2half2_rn(v0, v1);
                __half2 h1 = __floats2half2_rn(v2, v3);
                *(__half2*)(C + (long long)r0 * ldC + c)       = h0;
                *(__half2*)(C + (long long)(r0 + 8) * ldC + c) = h1;
            } else if (OUTMODE == 3) {   // VT[b][c][m], r0 global = b*2048+m
                __half* C = (__half*)Cv;
                const int b0 = r0 >> 11, mm = r0 & 2047;
                __half* base = C + (long long)b0 * (1024LL * 2048);
                base[(long long)c * 2048 + mm]           = __float2half_rn(v0);
                base[(long long)(c + 1) * 2048 + mm]     = __float2half_rn(v1);
                base[(long long)c * 2048 + mm + 8]       = __float2half_rn(v2);
                base[(long long)(c + 1) * 2048 + mm + 8] = __float2half_rn(v3);
            } else if (OUTMODE == 4) {   // exp(logit-4) + rowsum
                v0 = __expf(v0 - 4.0f); v1 = __expf(v1 - 4.0f);
                v2 = __expf(v2 - 4.0f); v3 = __expf(v3 - 4.0f);
                rsum0 += v0 + v1; rsum1 += v2 + v3;
                __half* C = (__half*)Cv;
                __half2 h0 = __floats2half2_rn(v0, v1);
                __half2 h1 = __floats2half2_rn(v2, v3);
                *(__half2*)(C + (long long)r0 * ldC + c)       = h0;
                *(__half2*)(C + (long long)(r0 + 8) * ldC + c) = h1;
            } else {   // OUTMODE 5
                v0 *= inv0; v1 *= inv0; v2 *= inv1; v3 *= inv1;
                __half* C = (__half*)Cv;
                __half2 h0 = __floats2half2_rn(v0, v1);
                __half2 h1 = __floats2half2_rn(v2, v3);
                *(__half2*)(C + (long long)r0 * ldC + c)       = h0;
                *(__half2*)(C + (long long)(r0 + 8) * ldC + c) = h1;
            }
        }
        if (OUTMODE == 4) {
#pragma unroll
            for (int o = 1; o <= 2; o <<= 1) {
                rsum0 += __shfl_xor_sync(0xffffffffu, rsum0, o);
                rsum1 += __shfl_xor_sync(0xffffffffu, rsum1, o);
            }
            if (tg == 0) {
                atomicAdd(&aux[r0], rsum0);
                atomicAdd(&aux[r0 + 8], rsum1);
            }
        }
    }
}

// ---------------------------------------------------------------------------
// OUT-phase GEMM body (R10's proven 64x32-warp loop): C tile [128,64],
// fp32 row-major output. Smaller tiles -> better drain/last-wave packing.
// ---------------------------------------------------------------------------
__device__ __forceinline__ void gemm_body64(
    const __half* __restrict__ Ab, const __half* __restrict__ Bb,
    float* __restrict__ C, int K, int ldA, int ldB, int ldC,
    int bm0, int bn0)
{
    extern __shared__ char sm[];
    char* smA = sm;
    char* smB = sm + STAGES * A_STAGE;

    const int tid = threadIdx.x, wid = tid >> 5, lane = tid & 31;
    const int g = lane >> 2, tg = lane & 3;
    const int m0 = (wid >> 1) * 64;   // 2x2 warp grid, warp tile 64x32
    const int n0 = (wid & 1) * 32;

    const uint32_t smAu = smem_u32(smA);
    const uint32_t smBu = smem_u32(smB);

    auto issue = [&](int kt, int buf) {
#pragma unroll
        for (int p = 0; p < 8; p++) {          // A: 128 rows x 8 chunks
            const int id = p * NTHREADS + tid;
            const int row = id >> 3, ch = id & 7;
            cp16(smAu + buf * A_STAGE + row * 128 + ((ch ^ (row & 7)) * 16),
                 Ab + (long long)(bm0 + row) * ldA + kt * BK + ch * 8);
        }
#pragma unroll
        for (int p = 0; p < 4; p++) {          // B: 64 rows x 8 chunks
            const int id = p * NTHREADS + tid;
            const int row = id >> 3, ch = id & 7;
            cp16(smBu + buf * B_STAGE64 + row * 128 + ((ch ^ (row & 7)) * 16),
                 Bb + (long long)(bn0 + row) * ldB + kt * BK + ch * 8);
        }
        cp_commit();
    };

    const int akc = lane >> 4;
    const int bkc = (lane >> 3) & 1;
    uint32_t aOff[4]; int aR7[4];
#pragma unroll
    for (int mt = 0; mt < 4; mt++) {
        const int r = m0 + mt * 16 + (lane & 15);
        aOff[mt] = r * 128; aR7[mt] = r & 7;
    }
    uint32_t bOff[2]; int bR7[2];
#pragma unroll
    for (int j = 0; j < 2; j++) {
        const int r = n0 + j * 16 + (lane & 7) + ((lane >> 4) << 3);
        bOff[j] = r * 128; bR7[j] = r & 7;
    }

    float acc[4][4][4];
#pragma unroll
    for (int mt = 0; mt < 4; mt++)
#pragma unroll
        for (int nt = 0; nt < 4; nt++)
#pragma unroll
            for (int i = 0; i < 4; i++) acc[mt][nt][i] = 0.f;

    const int NKT = K / BK;
    issue(0, 0);
    issue(1, 1);

    for (int kt = 0; kt < NKT; kt++) {
        cp_wait<STAGES - 2>();
        __syncthreads();

        const int buf = kt % STAGES;
        const uint32_t ab = smAu + buf * A_STAGE;
        const uint32_t bb = smBu + buf * B_STAGE64;

        uint32_t af[2][4][4], bf[2][2][4];
        auto ldfr = [&](int ks, int slot) {
#pragma unroll
            for (int mt = 0; mt < 4; mt++)
                ldsm4(af[slot][mt], ab + aOff[mt] + (((ks * 2 + akc) ^ aR7[mt]) * 16));
#pragma unroll
            for (int j = 0; j < 2; j++)
                ldsm4(bf[slot][j], bb + bOff[j] + (((ks * 2 + bkc) ^ bR7[j]) * 16));
        };

        ldfr(0, 0);
        const int nxt = kt + STAGES - 1;
        if (nxt < NKT) issue(nxt, nxt % STAGES);
        else cp_commit();

#pragma unroll
        for (int ks = 0; ks < 4; ks++) {
            const int cur = ks & 1;
            if (ks < 3) ldfr(ks + 1, cur ^ 1);
#pragma unroll
            for (int mt = 0; mt < 4; mt++)
#pragma unroll
                for (int nt = 0; nt < 4; nt++)
                    mma_f16(acc[mt][nt], af[cur][mt], &bf[cur][nt >> 1][(nt & 1) * 2]);
        }
    }

    // Epilogue: fp32 row-major
#pragma unroll
    for (int mt = 0; mt < 4; mt++) {
        const int r0 = bm0 + m0 + mt * 16 + g;
#pragma unroll
        for (int nt = 0; nt < 4; nt++) {
            const int c = bn0 + n0 + nt * 8 + 2 * tg;
            *(float2*)(C + (long long)r0 * ldC + c) =
                make_float2(acc[mt][nt][0], acc[mt][nt][1]);
            *(float2*)(C + (long long)(r0 + 8) * ldC + c) =
                make_float2(acc[mt][nt][2], acc[mt][nt][3]);
        }
    }
}

// ---------------------------------------------------------------------------
// The mega-kernel. Bid space:
//   [0,320)     convert (W bids 0..63 also zero Ssum; X/M per-chunk ctrs)
//   [320,832)   Q proj   (mb 0..63, nb 0..7)
//   [832,1344)  K proj
//   [1344,1856) VT proj
//   [1856,2880) logits   (b, i 0..15, j 0..15)
//   [2880,3392) PV       (b, i 0..15, j 0..7)
//   [3392,4416) out      (mb 0..63, nb 0..15; 128x64 tiles)
// ---------------------------------------------------------------------------
__global__ __launch_bounds__(NTHREADS, 2) void mega(
    const float* __restrict__ in0, const float* __restrict__ in1,
    const float* __restrict__ wq, const float* __restrict__ wk,
    const float* __restrict__ wv, const float* __restrict__ wo,
    __half* __restrict__ Xh, __half* __restrict__ Mh, __half* __restrict__ Wh,
    __half* __restrict__ Q, __half* __restrict__ Kp, __half* __restrict__ VT,
    __half* __restrict__ S, __half* __restrict__ O,
    float* __restrict__ out, float* __restrict__ Ssum, int* __restrict__ ctr)
{
    const int bid = blockIdx.x;

    if (bid < 320) {
        // ---- convert segment: 65536 floats (64 rows) per bid ----
        const float* src; __half* dst; float scale = 1.f; int cidx; long long c;
        if (bid < 64) {
            const int w = bid >> 4; c = bid & 15;
            src = (w == 0) ? wq : (w == 1) ? wk : (w == 2) ? wv : wo;
            dst = Wh + (long long)w * 1048576; cidx = w;
            if (w == 0) scale = 0.03125f;   // qscale folded, exact 2^-5
            Ssum[bid * 128 + threadIdx.x] = 0.0f;   // zero Ssum
        } else if (bid < 192) {
            c = bid - 64;  src = in0; dst = Xh;
            cidx = 8 + (int)(c >> 1);       // per-128-row-slice counter (tgt2)
        } else {
            c = bid - 192; src = in1; dst = Mh;
            cidx = 72 + (int)(c >> 1);
        }
        const float4* s4 = (const float4*)src + c * 16384;
        uint2* d4 = (uint2*)dst + c * 16384;
#pragma unroll 4
        for (int i = threadIdx.x; i < 16384; i += NTHREADS) {
            float4 v = s4[i];
            __half2 h0 = __floats2half2_rn(v.x * scale, v.y * scale);
            __half2 h1 = __floats2half2_rn(v.z * scale, v.w * scale);
            d4[i] = make_uint2(*(uint32_t*)&h0, *(uint32_t*)&h1);
        }
        __threadfence();
        __syncthreads();
        if (threadIdx.x == 0) {
            atomicAdd(&ctr[cidx], 1);
            if (bid < 64) atomicAdd(&ctr[6], 1);
        }
        return;
    }

    if (bid < 832) {
        // ---- Q projection: Q = Xh @ Wq^T ----
        const int t = bid - 320, mb = t >> 3, nb = t & 7;
        waitc(&ctr[0], 16);
        waitc(&ctr[8 + mb], 2);
        gemm_body<0>(Xh, Wh, Q, 1024, 1024, 1024, 1024, mb * 128, nb * 128, nullptr);
        bump(&ctr[136 + mb]);
        return;
    }
    if (bid < 1344) {
        // ---- K projection: K = Mh @ Wk^T ----
        const int t = bid - 832, mb = t >> 3, nb = t & 7;
        waitc(&ctr[1], 16);
        waitc(&ctr[72 + mb], 2);
        gemm_body<0>(Mh, Wh + 1048576, Kp, 1024, 1024, 1024, 1024,
                     mb * 128, nb * 128, nullptr);
        bump(&ctr[200 + mb]);
        return;
    }
    if (bid < 1856) {
        // ---- VT projection (transposed store): VT[b][d][m] ----
        const int t = bid - 1344, mb = t >> 3, nb = t & 7;
        waitc(&ctr[2], 16);
        waitc(&ctr[72 + mb], 2);
        gemm_body<3>(Mh, Wh + 2097152, VT, 1024, 1024, 1024, 0,
                     mb * 128, nb * 128, nullptr);
        bump(&ctr[264 + (mb >> 4) * 8 + nb]);
        return;
    }
    if (bid < 2880) {
        // ---- logits: E = exp(Q K^T - 4), Ssum accumulation ----
        const int t = bid - 1856, b = t >> 8, rem = t & 255, i = rem >> 4, j = rem & 15;
        waitc(&ctr[6], 64);
        waitc(&ctr[136 + b * 16 + i], 8);
        waitc(&ctr[200 + b * 16 + j], 8);
        gemm_body<4>(Q + (long long)b * 2048 * 1024, Kp + (long long)b * 2048 * 1024,
                     S + (long long)b * 2048 * 2048, 1024, 1024, 1024, 2048,
                     i * 128, j * 128, Ssum + b * 2048);
        bump(&ctr[296 + b * 16 + i]);
        return;
    }
    if (bid < 3392) {
        // ---- PV: O = (E @ VT^T) / Ssum ----
        const int t = bid - 2880, b = t >> 7, rem = t & 127, i = rem >> 3, j = rem & 7;
        waitc(&ctr[296 + b * 16 + i], 16);
        waitc(&ctr[264 + b * 8 + j], 16);
        gemm_body<5>(S + (long long)b * 2048 * 2048, VT + (long long)b * 1024 * 2048,
                     O + (long long)b * 2048 * 1024, 2048, 2048, 2048, 1024,
                     i * 128, j * 128, Ssum + b * 2048);
        bump(&ctr[360 + b * 16 + i]);
        return;
    }
    {
        // ---- out = O @ Wo^T (fp32), 128x64 tiles ----
        const int t = bid - 3392, mb = t >> 4, nb = t & 15;
        waitc(&ctr[360 + mb], 8);
        waitc(&ctr[3], 16);
        gemm_body64(O, Wh + 3145728, out, 1024, 1024, 1024, 1024,
                    mb * 128, nb * 64);
    }
}

extern "C" void kernel_launch(void* const* d_in, const int* in_sizes, int n_in,
                              void* d_out, int out_size)
{
    const float* input  = (const float*)d_in[0];
    const float* memory = (const float*)d_in[1];
    const float* Wq     = (const float*)d_in[2];
    const float* Wk     = (const float*)d_in[3];
    const float* Wv     = (const float*)d_in[4];
    const float* Wo     = (const float*)d_in[5];
    float* out = (float*)d_out;

    __half *Q, *K, *VT, *O, *S, *Xh, *Mh, *Wh;
    float* Ssum; int* ctr;
    cudaGetSymbolAddress((void**)&Q,  g_Q);
    cudaGetSymbolAddress((void**)&K,  g_K);
    cudaGetSymbolAddress((void**)&VT, g_VT);
    cudaGetSymbolAddress((void**)&O,  g_O);
    cudaGetSymbolAddress((void**)&S,  g_S);
    cudaGetSymbolAddress((void**)&Ssum, g_Ssum);
    cudaGetSymbolAddress((void**)&ctr,  g_ctr);
    cudaGetSymbolAddress((void**)&Xh, g_Xh);
    cudaGetSymbolAddress((void**)&Mh, g_Mh);
    cudaGetSymbolAddress((void**)&Wh, g_Wh);

    cudaFuncSetAttribute(mega, cudaFuncAttributeMaxDynamicSharedMemorySize, SMEM_BYTES);

    // Zero counters (graph-capturable). Ssum is zeroed inside the kernel.
    cudaMemsetAsync(ctr, 0, 424 * sizeof(int));

    // One launch: everything, dependency-overlapped.
    mega<<<4416, NTHREADS, SMEM_BYTES>>>(
        input, memory, Wq, Wk, Wv, Wo,
        Xh, Mh, Wh, Q, K, VT, S, O, out, Ssum, ctr);
}

// round 15
// speedup vs baseline: 1.0604x; 1.0604x over previous
#include <cuda_runtime.h>
#include <cuda_fp16.h>
#include <cstdint>

// ===========================================================================
// ScaledAttention on GB300 (compute_103 target -> legacy mma.sync path).
// R15 = R13 (best, 354.9us) + micro-opts in the GEMM mainloop:
//   - modulo-free buffer index counters (no % STAGES chains)
//   - hoisted per-thread cp.async src/dst base addressing (p-invariant
//     swizzle: ch and row&7 don't depend on p for 128-thread staging)
// One dependency-overlapped mega-kernel (bid-ordered, counter-synced).
// fp16 operands, fp32 accumulate, warp 64x64, CTA 128x128, 2 CTAs/SM.
// B=4, Lq=Lm=2048, D=1024.
// ===========================================================================

#define STAGES 3
#define BM 128
#define BN 128
#define BK 64
#define NTHREADS 128
#define A_STAGE (BM * BK * 2)                       // 16384 B
#define B_STAGE (BN * BK * 2)                       // 16384 B
#define SMEM_BYTES (STAGES * (A_STAGE + B_STAGE))   // 98304 B -> 2 CTAs/SM

// Scratch (allocation-free rule: __device__ globals)
__device__ __half g_Q [8192 * 1024];
__device__ __half g_K [8192 * 1024];
__device__ __half g_VT[4][1024 * 2048];    // V^T per batch: [d][m]
__device__ __half g_O [8192 * 1024];
__device__ __half g_S [4LL * 2048 * 2048]; // E = exp(logit-4)
__device__ float  g_Ssum[4 * 2048];
__device__ __half g_Xh[8192 * 1024];
__device__ __half g_Mh[8192 * 1024];
__device__ __half g_Wh[4][1024 * 1024];
// Counters:
// [0..3]    W conv (tgt16)
// [6]       Ssum zero (tgt64)
// [8..71]   X conv per-mb (128-row slice; tgt2)
// [72..135] M conv per-mb (tgt2)
// [136..199] Q rowblk (tgt8)
// [200..263] K rowblk (tgt8)
// [264..295] VT (b*8+dblk) (tgt16)
// [296..359] E rowblk (tgt16)
// [360..423] O rowblk (tgt8)
__device__ int g_ctr[424];

__device__ __forceinline__ uint32_t smem_u32(const void* p) {
    uint32_t a;
    asm("{ .reg .u64 t; cvta.to.shared.u64 t, %1; cvt.u32.u64 %0, t; }"
        : "=r"(a) : "l"(p));
    return a;
}
__device__ __forceinline__ void cp16(uint32_t dst, const void* src) {
    asm volatile("cp.async.cg.shared.global [%0], [%1], 16;"
                 :: "r"(dst), "l"(src) : "memory");
}
__device__ __forceinline__ void cp_commit() {
    asm volatile("cp.async.commit_group;" ::: "memory");
}
template <int N>
__device__ __forceinline__ void cp_wait() {
    asm volatile("cp.async.wait_group %0;" :: "n"(N) : "memory");
}
__device__ __forceinline__ void ldsm4(uint32_t* r, uint32_t addr) {
    asm volatile("ldmatrix.sync.aligned.m8n8.x4.shared.b16 {%0,%1,%2,%3}, [%4];"
                 : "=r"(r[0]), "=r"(r[1]), "=r"(r[2]), "=r"(r[3]) : "r"(addr));
}
__device__ __forceinline__ void mma_f16(float* c, const uint32_t* a, const uint32_t* b) {
    asm volatile(
        "mma.sync.aligned.m16n8k16.row.col.f32.f16.f16.f32 "
        "{%0,%1,%2,%3}, {%4,%5,%6,%7}, {%8,%9}, {%0,%1,%2,%3};"
        : "+f"(c[0]), "+f"(c[1]), "+f"(c[2]), "+f"(c[3])
        : "r"(a[0]), "r"(a[1]), "r"(a[2]), "r"(a[3]), "r"(b[0]), "r"(b[1]));
}

// Consumer: acquire-spin until *c >= tgt.
__device__ __forceinline__ void waitc(const int* c, int tgt) {
    if (threadIdx.x == 0) {
        int v;
        for (;;) {
            asm volatile("ld.global.acquire.gpu.b32 %0, [%1];" : "=r"(v) : "l"(c));
            if (v >= tgt) break;
            __nanosleep(128);
        }
    }
    __syncthreads();
}
// Producer: fence stores, then one thread bumps the counter.
__device__ __forceinline__ void bump(int* c) {
    __threadfence();
    __syncthreads();
    if (threadIdx.x == 0) atomicAdd(c, 1);
}

// ---------------------------------------------------------------------------
// GEMM body (R13 structure + micro-opts): C tile [128,128] = A[M,K] @ B^T.
// 4 warps in 2x2 of 64x64.
// OUTMODE 0: fp16 C row-major
// OUTMODE 2: fp32 C row-major
// OUTMODE 3: fp16 VT store (r0 = global row b*2048+m -> VT[b][c][m])
// OUTMODE 4: logits: store exp(acc-4) fp16 + atomicAdd row sums into aux
// OUTMODE 5: PV: multiply by 1/aux[row] before fp16 store
// ---------------------------------------------------------------------------
template <int OUTMODE>
__device__ __forceinline__ void gemm_body(
    const __half* __restrict__ Ab, const __half* __restrict__ Bb,
    void* __restrict__ Cv, int K, int ldA, int ldB, int ldC,
    int bm0, int bn0, float* __restrict__ aux)
{
    extern __shared__ char sm[];
    char* smA = sm;
    char* smB = sm + STAGES * A_STAGE;

    const int tid = threadIdx.x, wid = tid >> 5, lane = tid & 31;
    const int g = lane >> 2, tg = lane & 3;
    const int m0 = (wid >> 1) * 64;   // 2x2 warp grid
    const int n0 = (wid & 1) * 64;

    const uint32_t smAu = smem_u32(smA);
    const uint32_t smBu = smem_u32(smB);

    // Hoisted staging addresses. With 128 threads: row = p*16 + (tid>>3),
    // ch = tid&7 (p-invariant), row&7 = (tid>>3)&7 (p-invariant, 16%8==0).
    const int r0t = tid >> 3, cht = tid & 7;
    const uint32_t dstOff = (uint32_t)(r0t * 128 + ((cht ^ (r0t & 7)) * 16));
    const __half* aBase = Ab + (long long)(bm0 + r0t) * ldA + cht * 8;
    const __half* bBase = Bb + (long long)(bn0 + r0t) * ldB + cht * 8;
    const long long aRow16 = 16LL * ldA, bRow16 = 16LL * ldB;

    auto issue = [&](int kt, int buf) {
        const __half* as = aBase + kt * BK;
        const __half* bs = bBase + kt * BK;
        const uint32_t ad = smAu + buf * A_STAGE + dstOff;
        const uint32_t bd = smBu + buf * B_STAGE + dstOff;
#pragma unroll
        for (int p = 0; p < 8; p++)
            cp16(ad + p * 2048, as + p * aRow16);
#pragma unroll
        for (int p = 0; p < 8; p++)
            cp16(bd + p * 2048, bs + p * bRow16);
        cp_commit();
    };

    const int akc = lane >> 4;
    const int bkc = (lane >> 3) & 1;
    uint32_t aOff[4]; int aR7[4];
#pragma unroll
    for (int mt = 0; mt < 4; mt++) {
        const int r = m0 + mt * 16 + (lane & 15);
        aOff[mt] = r * 128; aR7[mt] = r & 7;
    }
    uint32_t bOff[4]; int bR7[4];
#pragma unroll
    for (int j = 0; j < 4; j++) {
        const int r = n0 + j * 16 + (lane & 7) + ((lane >> 4) << 3);
        bOff[j] = r * 128; bR7[j] = r & 7;
    }

    float acc[4][8][4];
#pragma unroll
    for (int mt = 0; mt < 4; mt++)
#pragma unroll
        for (int nt = 0; nt < 8; nt++)
#pragma unroll
            for (int i = 0; i < 4; i++) acc[mt][nt][i] = 0.f;

    const int NKT = K / BK;
    issue(0, 0);
    issue(1, 1);

    int buf = 0;        // = kt % 3, maintained by increment-wrap
    int ibuf = 2;       // = (kt+2) % 3
    for (int kt = 0; kt < NKT; kt++) {
        cp_wait<STAGES - 2>();
        __syncthreads();   // single barrier per stage (skew-proof)

        const uint32_t ab = smAu + buf * A_STAGE;
        const uint32_t bb = smBu + buf * B_STAGE;

        uint32_t af[2][4][4], bf[2][4][4];
        auto ldfr = [&](int ks, int slot) {
#pragma unroll
            for (int mt = 0; mt < 4; mt++)
                ldsm4(af[slot][mt], ab + aOff[mt] + (((ks * 2 + akc) ^ aR7[mt]) * 16));
#pragma unroll
            for (int j = 0; j < 4; j++)
                ldsm4(bf[slot][j], bb + bOff[j] + (((ks * 2 + bkc) ^ bR7[j]) * 16));
        };

        // Fragment loads first; next-stage cp.async issue after (2-stage lead).
        ldfr(0, 0);
        const int nxt = kt + STAGES - 1;
        if (nxt < NKT) issue(nxt, ibuf);
        else cp_commit();

#pragma unroll
        for (int ks = 0; ks < 4; ks++) {
            const int cur = ks & 1;
            if (ks < 3) ldfr(ks + 1, cur ^ 1);
#pragma unroll
            for (int mt = 0; mt < 4; mt++)
#pragma unroll
                for (int nt = 0; nt < 8; nt++)
                    mma_f16(acc[mt][nt], af[cur][mt], &bf[cur][nt >> 1][(nt & 1) * 2]);
        }

        buf  = (buf  == STAGES - 1) ? 0 : buf + 1;
        ibuf = (ibuf == STAGES - 1) ? 0 : ibuf + 1;
    }

    // Epilogue
#pragma unroll
    for (int mt = 0; mt < 4; mt++) {
        const int r0 = bm0 + m0 + mt * 16 + g;
        float inv0 = 1.f, inv1 = 1.f;
        if (OUTMODE == 5) {
            inv0 = 1.0f / aux[r0];
            inv1 = 1.0f / aux[r0 + 8];
        }
        float rsum0 = 0.f, rsum1 = 0.f;
#pragma unroll
        for (int nt = 0; nt < 8; nt++) {
            const int c = bn0 + n0 + nt * 8 + 2 * tg;
            float v0 = acc[mt][nt][0], v1 = acc[mt][nt][1];
            float v2 = acc[mt][nt][2], v3 = acc[mt][nt][3];
            if (OUTMODE == 0) {
                __half* C = (__half*)Cv;
                __half2 h0 = __floats2half2_rn(v0, v1);
                __half2 h1 = __floats2half2_rn(v2, v3);
                *(__half2*)(C + (long long)r0 * ldC + c)       = h0;
                *(__half2*)(C + (long long)(r0 + 8) * ldC + c) = h1;
            } else if (OUTMODE == 2) {
                float* C = (float*)Cv;
                *(float2*)(C + (long long)r0 * ldC + c)       = make_float2(v0, v1);
                *(float2*)(C + (long long)(r0 + 8) * ldC + c) = make_float2(v2, v3);
            } else if (OUTMODE == 3) {   // VT[b][c][m], r0 global = b*2048+m
                __half* C = (__half*)Cv;
                const int b0 = r0 >> 11, mm = r0 & 2047;
                __half* base = C + (long long)b0 * (1024LL * 2048);
                base[(long long)c * 2048 + mm]           = __float2half_rn(v0);
                base[(long long)(c + 1) * 2048 + mm]     = __float2half_rn(v1);
                base[(long long)c * 2048 + mm + 8]       = __float2half_rn(v2);
                base[(long long)(c + 1) * 2048 + mm + 8] = __float2half_rn(v3);
            } else if (OUTMODE == 4) {   // exp(logit-4) + rowsum
                v0 = __expf(v0 - 4.0f); v1 = __expf(v1 - 4.0f);
                v2 = __expf(v2 - 4.0f); v3 = __expf(v3 - 4.0f);
                rsum0 += v0 + v1; rsum1 += v2 + v3;
                __half* C = (__half*)Cv;
                __half2 h0 = __floats2half2_rn(v0, v1);
                __half2 h1 = __floats2half2_rn(v2, v3);
                *(__half2*)(C + (long long)r0 * ldC + c)       = h0;
                *(__half2*)(C + (long long)(r0 + 8) * ldC + c) = h1;
            } else {   // OUTMODE 5
                v0 *= inv0; v1 *= inv0; v2 *= inv1; v3 *= inv1;
                __half* C = (__half*)Cv;
                __half2 h0 = __floats2half2_rn(v0, v1);
                __half2 h1 = __floats2half2_rn(v2, v3);
                *(__half2*)(C + (long long)r0 * ldC + c)       = h0;
                *(__half2*)(C + (long long)(r0 + 8) * ldC + c) = h1;
            }
        }
        if (OUTMODE == 4) {
#pragma unroll
            for (int o = 1; o <= 2; o <<= 1) {
                rsum0 += __shfl_xor_sync(0xffffffffu, rsum0, o);
                rsum1 += __shfl_xor_sync(0xffffffffu, rsum1, o);
            }
            if (tg == 0) {
                atomicAdd(&aux[r0], rsum0);
                atomicAdd(&aux[r0 + 8], rsum1);
            }
        }
    }
}

// ---------------------------------------------------------------------------
// The mega-kernel. Bid space (R13 layout):
//   [0,320)     convert (W bids 0..63 also zero Ssum; X/M per-chunk ctrs)
//   [320,832)   Q proj   (mb 0..63, nb 0..7)
//   [832,1344)  K proj
//   [1344,1856) VT proj
//   [1856,2880) logits   (b, i 0..15, j 0..15)
//   [2880,3392) PV       (b, i 0..15, j 0..7)
//   [3392,3904) out      (mb 0..63, nb 0..7)
// ---------------------------------------------------------------------------
__global__ __launch_bounds__(NTHREADS, 2) void mega(
    const float* __restrict__ in0, const float* __restrict__ in1,
    const float* __restrict__ wq, const float* __restrict__ wk,
    const float* __restrict__ wv, const float* __restrict__ wo,
    __half* __restrict__ Xh, __half* __restrict__ Mh, __half* __restrict__ Wh,
    __half* __restrict__ Q, __half* __restrict__ Kp, __half* __restrict__ VT,
    __half* __restrict__ S, __half* __restrict__ O,
    float* __restrict__ out, float* __restrict__ Ssum, int* __restrict__ ctr)
{
    const int bid = blockIdx.x;

    if (bid < 320) {
        // ---- convert segment: 65536 floats (64 rows) per bid ----
        const float* src; __half* dst; float scale = 1.f; int cidx; long long c;
        if (bid < 64) {
            const int w = bid >> 4; c = bid & 15;
            src = (w == 0) ? wq : (w == 1) ? wk : (w == 2) ? wv : wo;
            dst = Wh + (long long)w * 1048576; cidx = w;
            if (w == 0) scale = 0.03125f;   // qscale folded, exact 2^-5
            Ssum[bid * 128 + threadIdx.x] = 0.0f;   // zero Ssum
        } else if (bid < 192) {
            c = bid - 64;  src = in0; dst = Xh;
            cidx = 8 + (int)(c >> 1);       // per-128-row-slice counter (tgt2)
        } else {
            c = bid - 192; src = in1; dst = Mh;
            cidx = 72 + (int)(c >> 1);
        }
        const float4* s4 = (const float4*)src + c * 16384;
        uint2* d4 = (uint2*)dst + c * 16384;
#pragma unroll 4
        for (int i = threadIdx.x; i < 16384; i += NTHREADS) {
            float4 v = s4[i];
            __half2 h0 = __floats2half2_rn(v.x * scale, v.y * scale);
            __half2 h1 = __floats2half2_rn(v.z * scale, v.w * scale);
            d4[i] = make_uint2(*(uint32_t*)&h0, *(uint32_t*)&h1);
        }
        __threadfence();
        __syncthreads();
        if (threadIdx.x == 0) {
            atomicAdd(&ctr[cidx], 1);
            if (bid < 64) atomicAdd(&ctr[6], 1);
        }
        return;
    }

    if (bid < 832) {
        // ---- Q projection: Q = Xh @ Wq^T ----
        const int t = bid - 320, mb = t >> 3, nb = t & 7;
        waitc(&ctr[0], 16);
        waitc(&ctr[8 + mb], 2);
        gemm_body<0>(Xh, Wh, Q, 1024, 1024, 1024, 1024, mb * 128, nb * 128, nullptr);
        bump(&ctr[136 + mb]);
        return;
    }
    if (bid < 1344) {
        // ---- K projection: K = Mh @ Wk^T ----
        const int t = bid - 832, mb = t >> 3, nb = t & 7;
        waitc(&ctr[1], 16);
        waitc(&ctr[72 + mb], 2);
        gemm_body<0>(Mh, Wh + 1048576, Kp, 1024, 1024, 1024, 1024,
                     mb * 128, nb * 128, nullptr);
        bump(&ctr[200 + mb]);
        return;
    }
    if (bid < 1856) {
        // ---- VT projection (transposed store): VT[b][d][m] ----
        const int t = bid - 1344, mb = t >> 3, nb = t & 7;
        waitc(&ctr[2], 16);
        waitc(&ctr[72 + mb], 2);
        gemm_body<3>(Mh, Wh + 2097152, VT, 1024, 1024, 1024, 0,
                     mb * 128, nb * 128, nullptr);
        bump(&ctr[264 + (mb >> 4) * 8 + nb]);
        return;
    }
    if (bid < 2880) {
        // ---- logits: E = exp(Q K^T - 4), Ssum accumulation ----
        const int t = bid - 1856, b = t >> 8, rem = t & 255, i = rem >> 4, j = rem & 15;
        waitc(&ctr[6], 64);
        waitc(&ctr[136 + b * 16 + i], 8);
        waitc(&ctr[200 + b * 16 + j], 8);
        gemm_body<4>(Q + (long long)b * 2048 * 1024, Kp + (long long)b * 2048 * 1024,
                     S + (long long)b * 2048 * 2048, 1024, 1024, 1024, 2048,
                     i * 128, j * 128, Ssum + b * 2048);
        bump(&ctr[296 + b * 16 + i]);
        return;
    }
    if (bid < 3392) {
        // ---- PV: O = (E @ VT^T) / Ssum ----
        const int t = bid - 2880, b = t >> 7, rem = t & 127, i = rem >> 3, j = rem & 7;
        waitc(&ctr[296 + b * 16 + i], 16);
        waitc(&ctr[264 + b * 8 + j], 16);
        gemm_body<5>(S + (long long)b * 2048 * 2048, VT + (long long)b * 1024 * 2048,
                     O + (long long)b * 2048 * 1024, 2048, 2048, 2048, 1024,
                     i * 128, j * 128, Ssum + b * 2048);
        bump(&ctr[360 + b * 16 + i]);
        return;
    }
    {
        // ---- out = O @ Wo^T (fp32), 128x128 tiles ----
        const int t = bid - 3392, mb = t >> 3, nb = t & 7;
        waitc(&ctr[360 + mb], 8);
        waitc(&ctr[3], 16);
        gemm_body<2>(O, Wh + 3145728, out, 1024, 1024, 1024, 1024,
                     mb * 128, nb * 128, nullptr);
    }
}

extern "C" void kernel_launch(void* const* d_in, const int* in_sizes, int n_in,
                              void* d_out, int out_size)
{
    const float* input  = (const float*)d_in[0];
    const float* memory = (const float*)d_in[1];
    const float* Wq     = (const float*)d_in[2];
    const float* Wk     = (const float*)d_in[3];
    const float* Wv     = (const float*)d_in[4];
    const float* Wo     = (const float*)d_in[5];
    float* out = (float*)d_out;

    __half *Q, *K, *VT, *O, *S, *Xh, *Mh, *Wh;
    float* Ssum; int* ctr;
    cudaGetSymbolAddress((void**)&Q,  g_Q);
    cudaGetSymbolAddress((void**)&K,  g_K);
    cudaGetSymbolAddress((void**)&VT, g_VT);
    cudaGetSymbolAddress((void**)&O,  g_O);
    cudaGetSymbolAddress((void**)&S,  g_S);
    cudaGetSymbolAddress((void**)&Ssum, g_Ssum);
    cudaGetSymbolAddress((void**)&ctr,  g_ctr);
    cudaGetSymbolAddress((void**)&Xh, g_Xh);
    cudaGetSymbolAddress((void**)&Mh, g_Mh);
    cudaGetSymbolAddress((void**)&Wh, g_Wh);

    cudaFuncSetAttribute(mega, cudaFuncAttributeMaxDynamicSharedMemorySize, SMEM_BYTES);

    // Zero counters (graph-capturable). Ssum is zeroed inside the kernel.
    cudaMemsetAsync(ctr, 0, 424 * sizeof(int));

    // One launch: everything, dependency-overlapped.
    mega<<<3904, NTHREADS, SMEM_BYTES>>>(
        input, memory, Wq, Wk, Wv, Wo,
        Xh, Mh, Wh, Q, K, VT, S, O, out, Ssum, ctr);
}